// round 15
// baseline (speedup 1.0000x reference)
#include <cuda_runtime.h>
#include <cuda_fp16.h>
#include <cstdint>
#include <math.h>

#define N_NODES 100000
#define NPAD    100064
#define FDIM    128
#define RNUM    3
#define NSEG    (RNUM * N_NODES)
#define CAP     64

// ---------------- scratch (device globals; no allocations allowed) ----------
__device__ __align__(16) __half g_act0[(size_t)NPAD * FDIM];  // x (fp16)
__device__ __align__(16) __half g_act1[(size_t)NPAD * FDIM];  // h1 = relu(L1)
__device__ __align__(16) __half g_act2[(size_t)NPAD * FDIM];  // h2 = relu(L2)
__device__ int   g_cnt[NSEG];
__device__ int   g_bkt[(size_t)NSEG * CAP];
__device__ __align__(16) unsigned char g_wh[8][32768];        // fp16 weights [mat][k][n]

// ---------------- prep ---------------------------------------------------------
__global__ void zero_cnt_kernel() {
    int i = blockIdx.x * blockDim.x + threadIdx.x;
    if (i < NSEG) g_cnt[i] = 0;
}
__global__ void count_fill_kernel(const int* __restrict__ src, const int* __restrict__ dst,
                                  const int* __restrict__ et, int E) {
    int e = blockIdx.x * blockDim.x + threadIdx.x;
    if (e < E) {
        int key = et[e] * N_NODES + dst[e];
        int slot = atomicAdd(&g_cnt[key], 1);
        if (slot < CAP) g_bkt[(size_t)key * CAP + slot] = src[e];
    }
}
__global__ void prep_w_kernel(const float* __restrict__ W1_rel, const float* __restrict__ W1_root,
                              const float* __restrict__ W2_rel, const float* __restrict__ W2_root) {
    int idx = blockIdx.x * blockDim.x + threadIdx.x;
    if (idx >= 8 * 16384) return;
    int mat = idx >> 14;
    int e = idx & 16383;
    int layer = mat >> 2, m = mat & 3;
    const float* W = (layer == 0)
        ? ((m == 0) ? W1_root : W1_rel + (size_t)(m - 1) * 16384)
        : ((m == 0) ? W2_root : W2_rel + (size_t)(m - 1) * 16384);
    *(__half*)(&g_wh[mat][e * 2]) = __float2half_rn(W[e]);
}
__global__ void cvt_x_kernel(const float* __restrict__ x, int n4) {
    int i = blockIdx.x * blockDim.x + threadIdx.x;
    if (i < n4) {
        float4 v = __ldg((const float4*)x + i);
        __half2 h0 = __floats2half2_rn(v.x, v.y);
        __half2 h1 = __floats2half2_rn(v.z, v.w);
        *(uint2*)(g_act0 + (size_t)i * 4) = make_uint2(*(uint32_t*)&h0, *(uint32_t*)&h1);
    }
}

// ---------------- mma helpers ------------------------------------------------
__device__ __forceinline__ uint32_t smem_u32(const void* p) {
    uint32_t a;
    asm("{ .reg .u64 t; cvta.to.shared.u64 t, %1; cvt.u32.u64 %0, t; }" : "=r"(a) : "l"(p));
    return a;
}
__device__ __forceinline__ void ldm_x4(uint32_t* r, uint32_t addr) {
    asm volatile("ldmatrix.sync.aligned.m8n8.x4.shared.b16 {%0,%1,%2,%3}, [%4];"
                 : "=r"(r[0]), "=r"(r[1]), "=r"(r[2]), "=r"(r[3]) : "r"(addr));
}
__device__ __forceinline__ void ldm_x4_t(uint32_t* r, uint32_t addr) {
    asm volatile("ldmatrix.sync.aligned.m8n8.x4.trans.shared.b16 {%0,%1,%2,%3}, [%4];"
                 : "=r"(r[0]), "=r"(r[1]), "=r"(r[2]), "=r"(r[3]) : "r"(addr));
}
__device__ __forceinline__ void mma_f16(float* c, const uint32_t* a, uint32_t b0, uint32_t b1) {
    asm volatile(
        "mma.sync.aligned.m16n8k16.row.col.f32.f16.f16.f32 "
        "{%0,%1,%2,%3}, {%4,%5,%6,%7}, {%8,%9}, {%0,%1,%2,%3};"
        : "+f"(c[0]), "+f"(c[1]), "+f"(c[2]), "+f"(c[3])
        : "r"(a[0]), "r"(a[1]), "r"(a[2]), "r"(a[3]), "r"(b0), "r"(b1));
}
__device__ __forceinline__ void cp_async16(uint32_t saddr, const void* gaddr) {
    asm volatile("cp.async.cg.shared.global [%0], [%1], 16;" :: "r"(saddr), "l"(gaddr));
}

// ---------------- fused layer: gather (to smem) + K=512 GEMM + relu -----------
// CTA = 64 rows, 512 threads (16 warps: 4m x 4n of 16x32 tiles), 1 CTA/SM.
// smem: bias 512B; A chunks c=0..3 (c0 = self, c1..3 = per-relation aggregates,
// built in-place by the gather phase); W chunks 0..3 all resident.
#define PITCHB  272
#define GA_B    (64 * PITCHB)               // 17408
#define GW_B    (128 * PITCHB)              // 34816
#define SM_BIAS 0
#define SM_A    512
#define SM_W    (SM_A + 4 * GA_B)           // 70144
#define SM_TOT  (SM_W + 4 * GW_B)           // 209408 B

template<int LAYER>
__global__ __launch_bounds__(512)
void layer_kernel(const float* __restrict__ bias, int Nn) {
    const __half* SRC = (LAYER == 1) ? g_act0 : g_act1;   // compile-time symbol
    __half* DST       = (LAYER == 1) ? g_act1 : g_act2;
    constexpr int matBase = (LAYER - 1) * 4;

    extern __shared__ unsigned char smem[];
    const uint32_t sb = smem_u32(smem);
    const int tid = threadIdx.x;
    const int wid = tid >> 5, lane = tid & 31;
    const int rowBase = blockIdx.x * 64;

    if (tid < 128) *(float*)(smem + SM_BIAS + tid * 4) = bias[tid];

    // --- async loads: A chunk 0 (self rows) + all 4 W chunks ---
    {
        const unsigned char* ag = (const unsigned char*)(SRC + (size_t)rowBase * FDIM);
#pragma unroll
        for (int i = 0; i < 2; ++i) {                     // 1024 x 16B
            int c = tid + 512 * i;
            cp_async16(sb + SM_A + (uint32_t)(c >> 4) * PITCHB + (c & 15) * 16, ag + c * 16);
        }
#pragma unroll
        for (int m = 0; m < 4; ++m) {
            const unsigned char* wg = g_wh[matBase + m];
#pragma unroll
            for (int i = 0; i < 4; ++i) {                 // 2048 x 16B
                int c = tid + 512 * i;
                cp_async16(sb + SM_W + m * GW_B + (uint32_t)(c >> 4) * PITCHB + (c & 15) * 16,
                           wg + c * 16);
            }
        }
        asm volatile("cp.async.commit_group;" ::: "memory");
    }

    // --- gather phase: 192 segments (64 rows x 3 relations) -> smem A chunks 1..3
    for (int s = wid; s < 192; s += 16) {
        int row = s & 63;
        int r = s >> 6;
        int d = rowBase + row;
        float4 acc4 = make_float4(0.f, 0.f, 0.f, 0.f);
        int cnt = 0;
        if (d < Nn) {
            int seg = r * N_NODES + d;
            cnt = __ldg(&g_cnt[seg]);
            if (cnt > CAP) cnt = CAP;
            const int* bkt = g_bkt + (size_t)seg * CAP;
            for (int i = 0; i < cnt; ++i) {
                int sn = __ldg(&bkt[i]);
                uint2 raw = __ldg((const uint2*)(SRC + (size_t)sn * FDIM) + lane);
                float2 v0 = __half22float2(*(__half2*)&raw.x);
                float2 v1 = __half22float2(*(__half2*)&raw.y);
                acc4.x += v0.x; acc4.y += v0.y; acc4.z += v1.x; acc4.w += v1.y;
            }
        }
        float iv = (cnt > 0) ? 1.0f / (float)cnt : 0.f;
        __half2 o0 = __floats2half2_rn(acc4.x * iv, acc4.y * iv);
        __half2 o1 = __floats2half2_rn(acc4.z * iv, acc4.w * iv);
        *(uint2*)(smem + SM_A + (1 + r) * GA_B + (uint32_t)row * PITCHB + lane * 8) =
            make_uint2(*(uint32_t*)&o0, *(uint32_t*)&o1);
    }

    asm volatile("cp.async.wait_group 0;" ::: "memory");
    __syncthreads();

    // --- MMA phase: warp tile 16 rows x 32 cols, K=512 over 4 chunks ---
    const int mw = (wid & 3) * 16;
    const int wn = (wid >> 2) * 32;
    const uint32_t lr = lane & 15, lb = lane >> 4;

    float acc[4][4];
#pragma unroll
    for (int b = 0; b < 4; ++b)
#pragma unroll
        for (int c = 0; c < 4; ++c) acc[b][c] = 0.f;

#pragma unroll
    for (int m = 0; m < 4; ++m) {
        const uint32_t abuf = SM_A + m * GA_B;
        const uint32_t wbuf = SM_W + m * GW_B;
#pragma unroll
        for (int k0 = 0; k0 < 128; k0 += 16) {
            uint32_t af[4], bf[4][2];
            ldm_x4(af, sb + abuf + (mw + lr) * PITCHB + (k0 + lb * 8) * 2);
#pragma unroll
            for (int nb2 = 0; nb2 < 2; ++nb2) {
                uint32_t r[4];
                ldm_x4_t(r, sb + wbuf + (k0 + lr) * PITCHB + (wn + nb2 * 16 + lb * 8) * 2);
                bf[nb2 * 2 + 0][0] = r[0]; bf[nb2 * 2 + 0][1] = r[1];
                bf[nb2 * 2 + 1][0] = r[2]; bf[nb2 * 2 + 1][1] = r[3];
            }
#pragma unroll
            for (int nt = 0; nt < 4; ++nt)
                mma_f16(acc[nt], af, bf[nt][0], bf[nt][1]);
        }
    }

    // --- epilogue: DST = fp16(relu(acc + bias)) ---
    {
        int r0 = rowBase + mw + (lane >> 2);
#pragma unroll
        for (int nt = 0; nt < 4; ++nt) {
            int col = wn + nt * 8 + (lane & 3) * 2;
            float bx = *(const float*)(smem + SM_BIAS + col * 4);
            float by = *(const float*)(smem + SM_BIAS + col * 4 + 4);
            if (r0 < Nn)
                *(__half2*)(DST + (size_t)r0 * FDIM + col) =
                    __floats2half2_rn(fmaxf(acc[nt][0] + bx, 0.f),
                                      fmaxf(acc[nt][1] + by, 0.f));
            if (r0 + 8 < Nn)
                *(__half2*)(DST + (size_t)(r0 + 8) * FDIM + col) =
                    __floats2half2_rn(fmaxf(acc[nt][2] + bx, 0.f),
                                      fmaxf(acc[nt][3] + by, 0.f));
        }
    }
}

// ---------------- head: g_act2 (relu'd h2) -> [128x2] -> log_softmax ----------
__global__ __launch_bounds__(256)
void head_kernel(const float* __restrict__ lin_w, const float* __restrict__ lin_b,
                 float* __restrict__ dout, int Nn) {
    __shared__ float w[256];
    __shared__ float b[2];
    if (threadIdx.x < 256) w[threadIdx.x] = lin_w[threadIdx.x];
    if (threadIdx.x < 2)   b[threadIdx.x] = lin_b[threadIdx.x];
    __syncthreads();

    int gtid = blockIdx.x * blockDim.x + threadIdx.x;
    int node = gtid >> 5;
    int lane = gtid & 31;
    if (node >= Nn) return;

    uint2 raw = __ldg((const uint2*)(g_act2 + (size_t)node * FDIM) + lane);
    float2 v0 = __half22float2(*(__half2*)&raw.x);
    float2 v1 = __half22float2(*(__half2*)&raw.y);

    int k = lane * 4;
    float a0 = v0.x * w[(k + 0) * 2] + v0.y * w[(k + 1) * 2] +
               v1.x * w[(k + 2) * 2] + v1.y * w[(k + 3) * 2];
    float a1 = v0.x * w[(k + 0) * 2 + 1] + v0.y * w[(k + 1) * 2 + 1] +
               v1.x * w[(k + 2) * 2 + 1] + v1.y * w[(k + 3) * 2 + 1];
#pragma unroll
    for (int o = 16; o > 0; o >>= 1) {
        a0 += __shfl_xor_sync(0xFFFFFFFFu, a0, o);
        a1 += __shfl_xor_sync(0xFFFFFFFFu, a1, o);
    }
    if (lane == 0) {
        float z0 = a0 + b[0];
        float z1 = a1 + b[1];
        float mx = fmaxf(z0, z1);
        float lse = mx + logf(expf(z0 - mx) + expf(z1 - mx));
        dout[(size_t)node * 2 + 0] = z0 - lse;
        dout[(size_t)node * 2 + 1] = z1 - lse;
    }
}

// ---------------- launch -------------------------------------------------------
extern "C" void kernel_launch(void* const* d_in, const int* in_sizes, int n_in,
                              void* d_out, int out_size) {
    const float* x       = (const float*)d_in[0];
    const int*   ei      = (const int*)  d_in[1];
    const int*   et      = (const int*)  d_in[2];
    const float* W1_rel  = (const float*)d_in[3];
    const float* W1_root = (const float*)d_in[4];
    const float* b1      = (const float*)d_in[5];
    const float* W2_rel  = (const float*)d_in[6];
    const float* W2_root = (const float*)d_in[7];
    const float* b2      = (const float*)d_in[8];
    const float* lin_w   = (const float*)d_in[9];
    const float* lin_b   = (const float*)d_in[10];

    const int Nn = in_sizes[0] / FDIM;   // 100000
    const int E  = in_sizes[1] / 2;      // 600000
    const int* srcp = ei;
    const int* dstp = ei + E;

    cudaFuncSetAttribute(layer_kernel<1>, cudaFuncAttributeMaxDynamicSharedMemorySize, SM_TOT);
    cudaFuncSetAttribute(layer_kernel<2>, cudaFuncAttributeMaxDynamicSharedMemorySize, SM_TOT);

    // prep
    zero_cnt_kernel<<<(NSEG + 255) / 256, 256>>>();
    count_fill_kernel<<<(E + 255) / 256, 256>>>(srcp, dstp, et, E);
    prep_w_kernel<<<512, 256>>>(W1_rel, W1_root, W2_rel, W2_root);
    cvt_x_kernel<<<(Nn * 32 + 255) / 256, 256>>>(x, Nn * 32);

    const int tiles64 = (Nn + 63) / 64;
    const int gblocks = (Nn * 32 + 255) / 256;

    layer_kernel<1><<<tiles64, 512, SM_TOT>>>(b1, Nn);
    layer_kernel<2><<<tiles64, 512, SM_TOT>>>(b2, Nn);
    head_kernel<<<gblocks, 256>>>(lin_w, lin_b, (float*)d_out, Nn);
}

// round 16
// speedup vs baseline: 1.4024x; 1.4024x over previous
#include <cuda_runtime.h>
#include <cuda_fp16.h>
#include <cstdint>
#include <math.h>

#define N_NODES 100000
#define NPAD    100064
#define FDIM    128
#define KBIG    512
#define RNUM    3
#define NSEG    (RNUM * N_NODES)
#define CAP     64

// ---------------- scratch (device globals; no allocations allowed) ----------
// g_abig[node][512] fp16: cols [0,128) = current activation (x -> h1 -> h2),
//                         cols [128+r*128, ...) = per-relation aggregate
__device__ __align__(16) __half g_abig[(size_t)NPAD * KBIG];
__device__ int   g_cnt[NSEG];
__device__ int   g_bkt[(size_t)NSEG * CAP];
__device__ __align__(16) unsigned char g_wh[8][32768];    // fp16 weights [mat][k][n]

// ---------------- prep ---------------------------------------------------------
__global__ void zero_cnt_kernel() {
    int i = blockIdx.x * blockDim.x + threadIdx.x;
    if (i < NSEG) g_cnt[i] = 0;
}
__global__ void count_fill_kernel(const int* __restrict__ src, const int* __restrict__ dst,
                                  const int* __restrict__ et, int E) {
    int e = blockIdx.x * blockDim.x + threadIdx.x;
    if (e < E) {
        int key = et[e] * N_NODES + dst[e];
        int slot = atomicAdd(&g_cnt[key], 1);
        if (slot < CAP) g_bkt[(size_t)key * CAP + slot] = src[e];
    }
}
__global__ void prep_w_kernel(const float* __restrict__ W1_rel, const float* __restrict__ W1_root,
                              const float* __restrict__ W2_rel, const float* __restrict__ W2_root) {
    int idx = blockIdx.x * blockDim.x + threadIdx.x;
    if (idx >= 8 * 16384) return;
    int mat = idx >> 14;
    int e = idx & 16383;
    int layer = mat >> 2, m = mat & 3;
    const float* W = (layer == 0)
        ? ((m == 0) ? W1_root : W1_rel + (size_t)(m - 1) * 16384)
        : ((m == 0) ? W2_root : W2_rel + (size_t)(m - 1) * 16384);
    *(__half*)(&g_wh[mat][e * 2]) = __float2half_rn(W[e]);
}
// x fp32 -> abig cols [0,128)
__global__ void cvt_x_kernel(const float* __restrict__ x, int n4) {
    int i = blockIdx.x * blockDim.x + threadIdx.x;
    if (i < n4) {
        int row = i >> 5;
        int c4 = (i & 31) * 4;
        float4 v = __ldg((const float4*)(x + (size_t)row * FDIM + c4));
        __half2 h0 = __floats2half2_rn(v.x, v.y);
        __half2 h1 = __floats2half2_rn(v.z, v.w);
        *(uint2*)(g_abig + (size_t)row * KBIG + c4) =
            make_uint2(*(uint32_t*)&h0, *(uint32_t*)&h1);
    }
}

// ---------------- gather: warp per (dst, relation) segment ---------------------
// abig[d][128+r*128+..] = mean over segment of abig[src][0..128)
__global__ __launch_bounds__(256)
void gather_kernel(int Nn) {
    int gtid = blockIdx.x * blockDim.x + threadIdx.x;
    int s = gtid >> 5;                  // segment id in [0, 3*Nn)
    int lane = gtid & 31;
    if (s >= RNUM * Nn) return;
    int r = s / Nn;
    int d = s - r * Nn;

    int seg = r * N_NODES + d;
    int cnt = __ldg(&g_cnt[seg]);
    if (cnt > CAP) cnt = CAP;

    // one coalesced bucket load, broadcast via shuffle (kills dependent chain)
    const int* bkt = g_bkt + (size_t)seg * CAP;
    int myidx = 0;
    if (lane < cnt) myidx = __ldg(&bkt[lane]);
    int myidx2 = 0;
    if (cnt > 32 && lane + 32 < cnt) myidx2 = __ldg(&bkt[lane + 32]);

    float4 acc = make_float4(0.f, 0.f, 0.f, 0.f);
    for (int i = 0; i < cnt; ++i) {
        int sn = (i < 32) ? __shfl_sync(0xFFFFFFFFu, myidx, i)
                          : __shfl_sync(0xFFFFFFFFu, myidx2, i - 32);
        uint2 raw = __ldg((const uint2*)(g_abig + (size_t)sn * KBIG) + lane);
        float2 v0 = __half22float2(*(__half2*)&raw.x);
        float2 v1 = __half22float2(*(__half2*)&raw.y);
        acc.x += v0.x; acc.y += v0.y; acc.z += v1.x; acc.w += v1.y;
    }
    float iv = (cnt > 0) ? 1.0f / (float)cnt : 0.f;
    __half2 o0 = __floats2half2_rn(acc.x * iv, acc.y * iv);
    __half2 o1 = __floats2half2_rn(acc.z * iv, acc.w * iv);
    *(uint2*)(g_abig + (size_t)d * KBIG + FDIM + r * FDIM + lane * 4) =
        make_uint2(*(uint32_t*)&o0, *(uint32_t*)&o1);
}

// ---------------- mma helpers ------------------------------------------------
__device__ __forceinline__ uint32_t smem_u32(const void* p) {
    uint32_t a;
    asm("{ .reg .u64 t; cvta.to.shared.u64 t, %1; cvt.u32.u64 %0, t; }" : "=r"(a) : "l"(p));
    return a;
}
__device__ __forceinline__ void ldm_x4(uint32_t* r, uint32_t addr) {
    asm volatile("ldmatrix.sync.aligned.m8n8.x4.shared.b16 {%0,%1,%2,%3}, [%4];"
                 : "=r"(r[0]), "=r"(r[1]), "=r"(r[2]), "=r"(r[3]) : "r"(addr));
}
__device__ __forceinline__ void ldm_x4_t(uint32_t* r, uint32_t addr) {
    asm volatile("ldmatrix.sync.aligned.m8n8.x4.trans.shared.b16 {%0,%1,%2,%3}, [%4];"
                 : "=r"(r[0]), "=r"(r[1]), "=r"(r[2]), "=r"(r[3]) : "r"(addr));
}
__device__ __forceinline__ void mma_f16(float* c, const uint32_t* a, uint32_t b0, uint32_t b1) {
    asm volatile(
        "mma.sync.aligned.m16n8k16.row.col.f32.f16.f16.f32 "
        "{%0,%1,%2,%3}, {%4,%5,%6,%7}, {%8,%9}, {%0,%1,%2,%3};"
        : "+f"(c[0]), "+f"(c[1]), "+f"(c[2]), "+f"(c[3])
        : "r"(a[0]), "r"(a[1]), "r"(a[2]), "r"(a[3]), "r"(b0), "r"(b1));
}
__device__ __forceinline__ void cp_async16(uint32_t saddr, const void* gaddr) {
    asm volatile("cp.async.cg.shared.global [%0], [%1], 16;" :: "r"(saddr), "l"(gaddr));
}

// ---------------- GEMM: out = abig[:,0:512] @ Wbig (K=512), 64-row CTA --------
#define PITCHB  272
#define GA_B    (64 * PITCHB)               // 17408
#define GW_B    (128 * PITCHB)              // 34816
#define SM_BIAS 0
#define SM_A0   512
#define SM_A1   (SM_A0 + GA_B)
#define SM_W0   (SM_A1 + GA_B)
#define SM_W1   (SM_W0 + GW_B)
#define SM_TOT  (SM_W1 + GW_B)              // 104960 B

__global__ __launch_bounds__(256)
void gemm_big_kernel(const float* __restrict__ bias, int Nn, int layer) {
    extern __shared__ unsigned char smem[];
    const uint32_t sb = smem_u32(smem);
    const int tid = threadIdx.x;
    const int wid = tid >> 5, lane = tid & 31;
    const int rowBase = blockIdx.x * 64;
    const int matBase = (layer - 1) * 4;

    if (tid < 128) *(float*)(smem + SM_BIAS + tid * 4) = bias[tid];

    // prefetch W chunk 0
    {
        const unsigned char* wg = g_wh[matBase];
#pragma unroll
        for (int i = 0; i < 8; ++i) {
            int c = tid + 256 * i;
            cp_async16(sb + SM_W0 + (uint32_t)(c >> 4) * PITCHB + (c & 15) * 16, wg + c * 16);
        }
        asm volatile("cp.async.commit_group;" ::: "memory");
    }
    // load A chunk 0 into regs, store to A buf 0
    uint4 a_st[4];
#pragma unroll
    for (int i = 0; i < 4; ++i) {
        int u = tid + 256 * i;                  // 1024 uint4 units
        int row = u >> 4, seg = u & 15;
        a_st[i] = __ldg((const uint4*)(g_abig + (size_t)(rowBase + row) * KBIG) + seg);
    }
#pragma unroll
    for (int i = 0; i < 4; ++i) {
        int u = tid + 256 * i;
        int row = u >> 4, seg = u & 15;
        *(uint4*)(smem + SM_A0 + (uint32_t)row * PITCHB + seg * 16) = a_st[i];
    }

    const int wm = (wid & 1) * 32;
    const int wn = (wid >> 1) * 32;
    const uint32_t lr = lane & 15, lb = lane >> 4;

    float acc[2][4][4];
#pragma unroll
    for (int a = 0; a < 2; ++a)
#pragma unroll
        for (int b = 0; b < 4; ++b)
#pragma unroll
            for (int c = 0; c < 4; ++c) acc[a][b][c] = 0.f;

    for (int m = 0; m < 4; ++m) {
        const uint32_t abuf = (m & 1) ? SM_A1 : SM_A0;
        const uint32_t wbuf = (m & 1) ? SM_W1 : SM_W0;
        if (m < 3) {
            const uint32_t nw = (m & 1) ? SM_W0 : SM_W1;
            const unsigned char* wg = g_wh[matBase + m + 1];
#pragma unroll
            for (int i = 0; i < 8; ++i) {
                int c = tid + 256 * i;
                cp_async16(sb + nw + (uint32_t)(c >> 4) * PITCHB + (c & 15) * 16, wg + c * 16);
            }
            asm volatile("cp.async.commit_group;" ::: "memory");
#pragma unroll
            for (int i = 0; i < 4; ++i) {
                int u = tid + 256 * i;
                int row = u >> 4, seg = u & 15;
                a_st[i] = __ldg((const uint4*)(g_abig + (size_t)(rowBase + row) * KBIG +
                                               (m + 1) * FDIM) + seg);
            }
            asm volatile("cp.async.wait_group 1;" ::: "memory");
        } else {
            asm volatile("cp.async.wait_group 0;" ::: "memory");
        }
        __syncthreads();

        if (m < 3) {
            const uint32_t na = (m & 1) ? SM_A0 : SM_A1;
#pragma unroll
            for (int i = 0; i < 4; ++i) {
                int u = tid + 256 * i;
                int row = u >> 4, seg = u & 15;
                *(uint4*)(smem + na + (uint32_t)row * PITCHB + seg * 16) = a_st[i];
            }
        }

#pragma unroll
        for (int k0 = 0; k0 < 128; k0 += 16) {
            uint32_t af[2][4], bf[4][2];
#pragma unroll
            for (int mt = 0; mt < 2; ++mt)
                ldm_x4(af[mt], sb + abuf + (wm + mt * 16 + lr) * PITCHB + (k0 + lb * 8) * 2);
#pragma unroll
            for (int nb2 = 0; nb2 < 2; ++nb2) {
                uint32_t r[4];
                ldm_x4_t(r, sb + wbuf + (k0 + lr) * PITCHB + (wn + nb2 * 16 + lb * 8) * 2);
                bf[nb2 * 2 + 0][0] = r[0]; bf[nb2 * 2 + 0][1] = r[1];
                bf[nb2 * 2 + 1][0] = r[2]; bf[nb2 * 2 + 1][1] = r[3];
            }
#pragma unroll
            for (int mt = 0; mt < 2; ++mt)
#pragma unroll
                for (int nt = 0; nt < 4; ++nt)
                    mma_f16(acc[mt][nt], af[mt], bf[nt][0], bf[nt][1]);
        }
        __syncthreads();
    }

    // epilogue: abig[:,0:128) = fp16(relu(acc + bias))
#pragma unroll
    for (int mt = 0; mt < 2; ++mt) {
        int r0 = rowBase + wm + mt * 16 + (lane >> 2);
#pragma unroll
        for (int nt = 0; nt < 4; ++nt) {
            int col = wn + nt * 8 + (lane & 3) * 2;
            float bx = *(const float*)(smem + SM_BIAS + col * 4);
            float by = *(const float*)(smem + SM_BIAS + col * 4 + 4);
            if (r0 < Nn)
                *(__half2*)(g_abig + (size_t)r0 * KBIG + col) =
                    __floats2half2_rn(fmaxf(acc[mt][nt][0] + bx, 0.f),
                                      fmaxf(acc[mt][nt][1] + by, 0.f));
            if (r0 + 8 < Nn)
                *(__half2*)(g_abig + (size_t)(r0 + 8) * KBIG + col) =
                    __floats2half2_rn(fmaxf(acc[mt][nt][2] + bx, 0.f),
                                      fmaxf(acc[mt][nt][3] + by, 0.f));
        }
    }
}

// ---------------- head: abig cols[0,128) (=h2, relu'd) -> [128x2] -> log_softmax
__global__ __launch_bounds__(256)
void head_kernel(const float* __restrict__ lin_w, const float* __restrict__ lin_b,
                 float* __restrict__ dout, int Nn) {
    __shared__ float w[256];
    __shared__ float b[2];
    if (threadIdx.x < 256) w[threadIdx.x] = lin_w[threadIdx.x];
    if (threadIdx.x < 2)   b[threadIdx.x] = lin_b[threadIdx.x];
    __syncthreads();

    int gtid = blockIdx.x * blockDim.x + threadIdx.x;
    int node = gtid >> 5;
    int lane = gtid & 31;
    if (node >= Nn) return;

    uint2 raw = __ldg((const uint2*)(g_abig + (size_t)node * KBIG) + lane);
    float2 v0 = __half22float2(*(__half2*)&raw.x);
    float2 v1 = __half22float2(*(__half2*)&raw.y);

    int k = lane * 4;
    float a0 = v0.x * w[(k + 0) * 2] + v0.y * w[(k + 1) * 2] +
               v1.x * w[(k + 2) * 2] + v1.y * w[(k + 3) * 2];
    float a1 = v0.x * w[(k + 0) * 2 + 1] + v0.y * w[(k + 1) * 2 + 1] +
               v1.x * w[(k + 2) * 2 + 1] + v1.y * w[(k + 3) * 2 + 1];
#pragma unroll
    for (int o = 16; o > 0; o >>= 1) {
        a0 += __shfl_xor_sync(0xFFFFFFFFu, a0, o);
        a1 += __shfl_xor_sync(0xFFFFFFFFu, a1, o);
    }
    if (lane == 0) {
        float z0 = a0 + b[0];
        float z1 = a1 + b[1];
        float mx = fmaxf(z0, z1);
        float lse = mx + logf(expf(z0 - mx) + expf(z1 - mx));
        dout[(size_t)node * 2 + 0] = z0 - lse;
        dout[(size_t)node * 2 + 1] = z1 - lse;
    }
}

// ---------------- launch -------------------------------------------------------
extern "C" void kernel_launch(void* const* d_in, const int* in_sizes, int n_in,
                              void* d_out, int out_size) {
    const float* x       = (const float*)d_in[0];
    const int*   ei      = (const int*)  d_in[1];
    const int*   et      = (const int*)  d_in[2];
    const float* W1_rel  = (const float*)d_in[3];
    const float* W1_root = (const float*)d_in[4];
    const float* b1      = (const float*)d_in[5];
    const float* W2_rel  = (const float*)d_in[6];
    const float* W2_root = (const float*)d_in[7];
    const float* b2      = (const float*)d_in[8];
    const float* lin_w   = (const float*)d_in[9];
    const float* lin_b   = (const float*)d_in[10];

    const int Nn = in_sizes[0] / FDIM;   // 100000
    const int E  = in_sizes[1] / 2;      // 600000
    const int* srcp = ei;
    const int* dstp = ei + E;

    cudaFuncSetAttribute(gemm_big_kernel, cudaFuncAttributeMaxDynamicSharedMemorySize, SM_TOT);

    // prep
    zero_cnt_kernel<<<(NSEG + 255) / 256, 256>>>();
    count_fill_kernel<<<(E + 255) / 256, 256>>>(srcp, dstp, et, E);
    prep_w_kernel<<<512, 256>>>(W1_rel, W1_root, W2_rel, W2_root);
    cvt_x_kernel<<<(Nn * 32 + 255) / 256, 256>>>(x, Nn * 32);

    const int segblocks = (RNUM * Nn * 32 + 255) / 256;
    const int gblocks = (Nn * 32 + 255) / 256;
    const int tiles64 = (Nn + 63) / 64;

    // layer 1
    gather_kernel<<<segblocks, 256>>>(Nn);
    gemm_big_kernel<<<tiles64, 256, SM_TOT>>>(b1, Nn, 1);

    // layer 2
    gather_kernel<<<segblocks, 256>>>(Nn);
    gemm_big_kernel<<<tiles64, 256, SM_TOT>>>(b2, Nn, 2);
    head_kernel<<<gblocks, 256>>>(lin_w, lin_b, (float*)d_out, Nn);
}

// round 17
// speedup vs baseline: 1.6197x; 1.1549x over previous
#include <cuda_runtime.h>
#include <cuda_fp16.h>
#include <cstdint>
#include <math.h>

#define N_NODES 100000
#define NPAD    100064
#define FDIM    128
#define KBIG    512
#define RNUM    3
#define NSEG    (RNUM * N_NODES)
#define CAP     64

// ---------------- scratch (device globals; no allocations allowed) ----------
// g_abig[node][512] fp16: cols [0,128) = current activation (x -> h1 -> h2),
//                         cols [128+r*128, ...) = per-relation aggregate
__device__ __align__(16) __half g_abig[(size_t)NPAD * KBIG];
__device__ int   g_cnt[NSEG];
__device__ int   g_bkt[(size_t)NSEG * CAP];
__device__ __align__(16) unsigned char g_wh[8][32768];    // fp16 weights [mat][k][n]

// ---------------- prep ---------------------------------------------------------
__global__ void zero_cnt_kernel() {
    int i = blockIdx.x * blockDim.x + threadIdx.x;
    if (i < NSEG) g_cnt[i] = 0;
}
__global__ void count_fill_kernel(const int* __restrict__ src, const int* __restrict__ dst,
                                  const int* __restrict__ et, int E) {
    int e = blockIdx.x * blockDim.x + threadIdx.x;
    if (e < E) {
        int key = et[e] * N_NODES + dst[e];
        int slot = atomicAdd(&g_cnt[key], 1);
        if (slot < CAP) g_bkt[(size_t)key * CAP + slot] = src[e];
    }
}
__global__ void prep_w_kernel(const float* __restrict__ W1_rel, const float* __restrict__ W1_root,
                              const float* __restrict__ W2_rel, const float* __restrict__ W2_root) {
    int idx = blockIdx.x * blockDim.x + threadIdx.x;
    if (idx >= 8 * 16384) return;
    int mat = idx >> 14;
    int e = idx & 16383;
    int layer = mat >> 2, m = mat & 3;
    const float* W = (layer == 0)
        ? ((m == 0) ? W1_root : W1_rel + (size_t)(m - 1) * 16384)
        : ((m == 0) ? W2_root : W2_rel + (size_t)(m - 1) * 16384);
    *(__half*)(&g_wh[mat][e * 2]) = __float2half_rn(W[e]);
}
// x fp32 -> abig cols [0,128)
__global__ void cvt_x_kernel(const float* __restrict__ x, int n4) {
    int i = blockIdx.x * blockDim.x + threadIdx.x;
    if (i < n4) {
        int row = i >> 5;
        int c4 = (i & 31) * 4;
        float4 v = __ldg((const float4*)(x + (size_t)row * FDIM + c4));
        __half2 h0 = __floats2half2_rn(v.x, v.y);
        __half2 h1 = __floats2half2_rn(v.z, v.w);
        *(uint2*)(g_abig + (size_t)row * KBIG + c4) =
            make_uint2(*(uint32_t*)&h0, *(uint32_t*)&h1);
    }
}

// ---------------- gather: warp per dst, 4x-unrolled edge loop ------------------
// abig[d][128+r*128+..] = mean over segment of abig[src][0..128)
__global__ __launch_bounds__(256)
void gather_kernel(int Nn) {
    int gtid = blockIdx.x * blockDim.x + threadIdx.x;
    int d = gtid >> 5;
    int lane = gtid & 31;
    if (d >= Nn) return;

#pragma unroll
    for (int r = 0; r < RNUM; ++r) {
        int seg = r * N_NODES + d;
        int cnt = __ldg(&g_cnt[seg]);
        if (cnt > CAP) cnt = CAP;
        const int* bkt = g_bkt + (size_t)seg * CAP;
        float4 s = make_float4(0.f, 0.f, 0.f, 0.f);
        int i = 0;
        // 4x unrolled: bucket loads independent, then 4 independent row loads (MLP=4)
        for (; i + 3 < cnt; i += 4) {
            int s0 = __ldg(&bkt[i + 0]);
            int s1 = __ldg(&bkt[i + 1]);
            int s2 = __ldg(&bkt[i + 2]);
            int s3 = __ldg(&bkt[i + 3]);
            uint2 q0 = __ldg((const uint2*)(g_abig + (size_t)s0 * KBIG) + lane);
            uint2 q1 = __ldg((const uint2*)(g_abig + (size_t)s1 * KBIG) + lane);
            uint2 q2 = __ldg((const uint2*)(g_abig + (size_t)s2 * KBIG) + lane);
            uint2 q3 = __ldg((const uint2*)(g_abig + (size_t)s3 * KBIG) + lane);
            float2 a0 = __half22float2(*(__half2*)&q0.x), b0 = __half22float2(*(__half2*)&q0.y);
            float2 a1 = __half22float2(*(__half2*)&q1.x), b1 = __half22float2(*(__half2*)&q1.y);
            float2 a2 = __half22float2(*(__half2*)&q2.x), b2 = __half22float2(*(__half2*)&q2.y);
            float2 a3 = __half22float2(*(__half2*)&q3.x), b3 = __half22float2(*(__half2*)&q3.y);
            s.x += (a0.x + a1.x) + (a2.x + a3.x);
            s.y += (a0.y + a1.y) + (a2.y + a3.y);
            s.z += (b0.x + b1.x) + (b2.x + b3.x);
            s.w += (b0.y + b1.y) + (b2.y + b3.y);
        }
        for (; i < cnt; ++i) {
            int sn = __ldg(&bkt[i]);
            uint2 raw = __ldg((const uint2*)(g_abig + (size_t)sn * KBIG) + lane);
            float2 v0 = __half22float2(*(__half2*)&raw.x);
            float2 v1 = __half22float2(*(__half2*)&raw.y);
            s.x += v0.x; s.y += v0.y; s.z += v1.x; s.w += v1.y;
        }
        float iv = (cnt > 0) ? 1.0f / (float)cnt : 0.f;
        __half2 o0 = __floats2half2_rn(s.x * iv, s.y * iv);
        __half2 o1 = __floats2half2_rn(s.z * iv, s.w * iv);
        *(uint2*)(g_abig + (size_t)d * KBIG + FDIM + r * FDIM + lane * 4) =
            make_uint2(*(uint32_t*)&o0, *(uint32_t*)&o1);
    }
}

// ---------------- mma helpers ------------------------------------------------
__device__ __forceinline__ uint32_t smem_u32(const void* p) {
    uint32_t a;
    asm("{ .reg .u64 t; cvta.to.shared.u64 t, %1; cvt.u32.u64 %0, t; }" : "=r"(a) : "l"(p));
    return a;
}
__device__ __forceinline__ void ldm_x4(uint32_t* r, uint32_t addr) {
    asm volatile("ldmatrix.sync.aligned.m8n8.x4.shared.b16 {%0,%1,%2,%3}, [%4];"
                 : "=r"(r[0]), "=r"(r[1]), "=r"(r[2]), "=r"(r[3]) : "r"(addr));
}
__device__ __forceinline__ void ldm_x4_t(uint32_t* r, uint32_t addr) {
    asm volatile("ldmatrix.sync.aligned.m8n8.x4.trans.shared.b16 {%0,%1,%2,%3}, [%4];"
                 : "=r"(r[0]), "=r"(r[1]), "=r"(r[2]), "=r"(r[3]) : "r"(addr));
}
__device__ __forceinline__ void mma_f16(float* c, const uint32_t* a, uint32_t b0, uint32_t b1) {
    asm volatile(
        "mma.sync.aligned.m16n8k16.row.col.f32.f16.f16.f32 "
        "{%0,%1,%2,%3}, {%4,%5,%6,%7}, {%8,%9}, {%0,%1,%2,%3};"
        : "+f"(c[0]), "+f"(c[1]), "+f"(c[2]), "+f"(c[3])
        : "r"(a[0]), "r"(a[1]), "r"(a[2]), "r"(a[3]), "r"(b0), "r"(b1));
}
__device__ __forceinline__ void cp_async16(uint32_t saddr, const void* gaddr) {
    asm volatile("cp.async.cg.shared.global [%0], [%1], 16;" :: "r"(saddr), "l"(gaddr));
}

// ---------------- GEMM: out = abig[:,0:512] @ Wbig (K=512), 64-row CTA --------
#define PITCHB  272
#define GA_B    (64 * PITCHB)               // 17408
#define GW_B    (128 * PITCHB)              // 34816
#define SM_BIAS 0
#define SM_A0   512
#define SM_A1   (SM_A0 + GA_B)
#define SM_W0   (SM_A1 + GA_B)
#define SM_W1   (SM_W0 + GW_B)
#define SM_TOT  (SM_W1 + GW_B)              // 104960 B

__global__ __launch_bounds__(256)
void gemm_big_kernel(const float* __restrict__ bias, int Nn, int layer) {
    extern __shared__ unsigned char smem[];
    const uint32_t sb = smem_u32(smem);
    const int tid = threadIdx.x;
    const int wid = tid >> 5, lane = tid & 31;
    const int rowBase = blockIdx.x * 64;
    const int matBase = (layer - 1) * 4;

    if (tid < 128) *(float*)(smem + SM_BIAS + tid * 4) = bias[tid];

    // prefetch W chunk 0
    {
        const unsigned char* wg = g_wh[matBase];
#pragma unroll
        for (int i = 0; i < 8; ++i) {
            int c = tid + 256 * i;
            cp_async16(sb + SM_W0 + (uint32_t)(c >> 4) * PITCHB + (c & 15) * 16, wg + c * 16);
        }
        asm volatile("cp.async.commit_group;" ::: "memory");
    }
    // load A chunk 0 into regs, store to A buf 0
    uint4 a_st[4];
#pragma unroll
    for (int i = 0; i < 4; ++i) {
        int u = tid + 256 * i;                  // 1024 uint4 units
        int row = u >> 4, seg = u & 15;
        a_st[i] = __ldg((const uint4*)(g_abig + (size_t)(rowBase + row) * KBIG) + seg);
    }
#pragma unroll
    for (int i = 0; i < 4; ++i) {
        int u = tid + 256 * i;
        int row = u >> 4, seg = u & 15;
        *(uint4*)(smem + SM_A0 + (uint32_t)row * PITCHB + seg * 16) = a_st[i];
    }

    const int wm = (wid & 1) * 32;
    const int wn = (wid >> 1) * 32;
    const uint32_t lr = lane & 15, lb = lane >> 4;

    float acc[2][4][4];
#pragma unroll
    for (int a = 0; a < 2; ++a)
#pragma unroll
        for (int b = 0; b < 4; ++b)
#pragma unroll
            for (int c = 0; c < 4; ++c) acc[a][b][c] = 0.f;

    for (int m = 0; m < 4; ++m) {
        const uint32_t abuf = (m & 1) ? SM_A1 : SM_A0;
        const uint32_t wbuf = (m & 1) ? SM_W1 : SM_W0;
        if (m < 3) {
            const uint32_t nw = (m & 1) ? SM_W0 : SM_W1;
            const unsigned char* wg = g_wh[matBase + m + 1];
#pragma unroll
            for (int i = 0; i < 8; ++i) {
                int c = tid + 256 * i;
                cp_async16(sb + nw + (uint32_t)(c >> 4) * PITCHB + (c & 15) * 16, wg + c * 16);
            }
            asm volatile("cp.async.commit_group;" ::: "memory");
#pragma unroll
            for (int i = 0; i < 4; ++i) {
                int u = tid + 256 * i;
                int row = u >> 4, seg = u & 15;
                a_st[i] = __ldg((const uint4*)(g_abig + (size_t)(rowBase + row) * KBIG +
                                               (m + 1) * FDIM) + seg);
            }
            asm volatile("cp.async.wait_group 1;" ::: "memory");
        } else {
            asm volatile("cp.async.wait_group 0;" ::: "memory");
        }
        __syncthreads();

        if (m < 3) {
            const uint32_t na = (m & 1) ? SM_A0 : SM_A1;
#pragma unroll
            for (int i = 0; i < 4; ++i) {
                int u = tid + 256 * i;
                int row = u >> 4, seg = u & 15;
                *(uint4*)(smem + na + (uint32_t)row * PITCHB + seg * 16) = a_st[i];
            }
        }

#pragma unroll
        for (int k0 = 0; k0 < 128; k0 += 16) {
            uint32_t af[2][4], bf[4][2];
#pragma unroll
            for (int mt = 0; mt < 2; ++mt)
                ldm_x4(af[mt], sb + abuf + (wm + mt * 16 + lr) * PITCHB + (k0 + lb * 8) * 2);
#pragma unroll
            for (int nb2 = 0; nb2 < 2; ++nb2) {
                uint32_t r[4];
                ldm_x4_t(r, sb + wbuf + (k0 + lr) * PITCHB + (wn + nb2 * 16 + lb * 8) * 2);
                bf[nb2 * 2 + 0][0] = r[0]; bf[nb2 * 2 + 0][1] = r[1];
                bf[nb2 * 2 + 1][0] = r[2]; bf[nb2 * 2 + 1][1] = r[3];
            }
#pragma unroll
            for (int mt = 0; mt < 2; ++mt)
#pragma unroll
                for (int nt = 0; nt < 4; ++nt)
                    mma_f16(acc[mt][nt], af[mt], bf[nt][0], bf[nt][1]);
        }
        __syncthreads();
    }

    // epilogue: abig[:,0:128) = fp16(relu(acc + bias))
#pragma unroll
    for (int mt = 0; mt < 2; ++mt) {
        int r0 = rowBase + wm + mt * 16 + (lane >> 2);
#pragma unroll
        for (int nt = 0; nt < 4; ++nt) {
            int col = wn + nt * 8 + (lane & 3) * 2;
            float bx = *(const float*)(smem + SM_BIAS + col * 4);
            float by = *(const float*)(smem + SM_BIAS + col * 4 + 4);
            if (r0 < Nn)
                *(__half2*)(g_abig + (size_t)r0 * KBIG + col) =
                    __floats2half2_rn(fmaxf(acc[mt][nt][0] + bx, 0.f),
                                      fmaxf(acc[mt][nt][1] + by, 0.f));
            if (r0 + 8 < Nn)
                *(__half2*)(g_abig + (size_t)(r0 + 8) * KBIG + col) =
                    __floats2half2_rn(fmaxf(acc[mt][nt][2] + bx, 0.f),
                                      fmaxf(acc[mt][nt][3] + by, 0.f));
        }
    }
}

// ---------------- head: abig cols[0,128) (=h2, relu'd) -> [128x2] -> log_softmax
__global__ __launch_bounds__(256)
void head_kernel(const float* __restrict__ lin_w, const float* __restrict__ lin_b,
                 float* __restrict__ dout, int Nn) {
    __shared__ float w[256];
    __shared__ float b[2];
    if (threadIdx.x < 256) w[threadIdx.x] = lin_w[threadIdx.x];
    if (threadIdx.x < 2)   b[threadIdx.x] = lin_b[threadIdx.x];
    __syncthreads();

    int gtid = blockIdx.x * blockDim.x + threadIdx.x;
    int node = gtid >> 5;
    int lane = gtid & 31;
    if (node >= Nn) return;

    uint2 raw = __ldg((const uint2*)(g_abig + (size_t)node * KBIG) + lane);
    float2 v0 = __half22float2(*(__half2*)&raw.x);
    float2 v1 = __half22float2(*(__half2*)&raw.y);

    int k = lane * 4;
    float a0 = v0.x * w[(k + 0) * 2] + v0.y * w[(k + 1) * 2] +
               v1.x * w[(k + 2) * 2] + v1.y * w[(k + 3) * 2];
    float a1 = v0.x * w[(k + 0) * 2 + 1] + v0.y * w[(k + 1) * 2 + 1] +
               v1.x * w[(k + 2) * 2 + 1] + v1.y * w[(k + 3) * 2 + 1];
#pragma unroll
    for (int o = 16; o > 0; o >>= 1) {
        a0 += __shfl_xor_sync(0xFFFFFFFFu, a0, o);
        a1 += __shfl_xor_sync(0xFFFFFFFFu, a1, o);
    }
    if (lane == 0) {
        float z0 = a0 + b[0];
        float z1 = a1 + b[1];
        float mx = fmaxf(z0, z1);
        float lse = mx + logf(expf(z0 - mx) + expf(z1 - mx));
        dout[(size_t)node * 2 + 0] = z0 - lse;
        dout[(size_t)node * 2 + 1] = z1 - lse;
    }
}

// ---------------- launch -------------------------------------------------------
extern "C" void kernel_launch(void* const* d_in, const int* in_sizes, int n_in,
                              void* d_out, int out_size) {
    const float* x       = (const float*)d_in[0];
    const int*   ei      = (const int*)  d_in[1];
    const int*   et      = (const int*)  d_in[2];
    const float* W1_rel  = (const float*)d_in[3];
    const float* W1_root = (const float*)d_in[4];
    const float* b1      = (const float*)d_in[5];
    const float* W2_rel  = (const float*)d_in[6];
    const float* W2_root = (const float*)d_in[7];
    const float* b2      = (const float*)d_in[8];
    const float* lin_w   = (const float*)d_in[9];
    const float* lin_b   = (const float*)d_in[10];

    const int Nn = in_sizes[0] / FDIM;   // 100000
    const int E  = in_sizes[1] / 2;      // 600000
    const int* srcp = ei;
    const int* dstp = ei + E;

    cudaFuncSetAttribute(gemm_big_kernel, cudaFuncAttributeMaxDynamicSharedMemorySize, SM_TOT);

    // prep
    zero_cnt_kernel<<<(NSEG + 255) / 256, 256>>>();
    count_fill_kernel<<<(E + 255) / 256, 256>>>(srcp, dstp, et, E);
    prep_w_kernel<<<512, 256>>>(W1_rel, W1_root, W2_rel, W2_root);
    cvt_x_kernel<<<(Nn * 32 + 255) / 256, 256>>>(x, Nn * 32);

    const int gblocks = (Nn * 32 + 255) / 256;
    const int tiles64 = (Nn + 63) / 64;

    // layer 1
    gather_kernel<<<gblocks, 256>>>(Nn);
    gemm_big_kernel<<<tiles64, 256, SM_TOT>>>(b1, Nn, 1);

    // layer 2
    gather_kernel<<<gblocks, 256>>>(Nn);
    gemm_big_kernel<<<tiles64, 256, SM_TOT>>>(b2, Nn, 2);
    head_kernel<<<gblocks, 256>>>(lin_w, lin_b, (float*)d_out, Nn);
}